// round 12
// baseline (speedup 1.0000x reference)
#include <cuda_runtime.h>
#include <cuda_bf16.h>
#include <cstdint>

#define NN 8192
#define FD 256
#define HD 64
#define NTC 72     // C columns (deg at col 64)
#define BM 128
#define BK 64
#define KSPLIT 4
#define NITL (NN / BK / KSPLIT)   // 32 k-tiles per CTA
#define SB_STR 72                 // bf16 per sB row (conflict-free trans ldmatrix)
#define SB_TILE (BK * SB_STR)     // 4608 bf16 = 9216 B
#define SA_BYTES (BM * 128)       // 16384 B per A stage (bf16, 128B rows)
#define SMEM_MM (2 * SA_BYTES + 3 * SB_TILE * 2)  // 60416

// device scratch (static allocation only — no cudaMalloc allowed)
__device__ __align__(16) __nv_bfloat16 g_hext[NN * HD];   // h bf16 [k][c]
__device__ __align__(16) float g_Cp[KSPLIT * NN * NTC];   // partial C (+deg col 64)

typedef unsigned int uint;

__device__ __forceinline__ void cpa16(void* dst, const void* src) {
    uint32_t d = (uint32_t)__cvta_generic_to_shared(dst);
    asm volatile("cp.async.cg.shared.global [%0], [%1], 16;\n" :: "r"(d), "l"(src));
}

// ---------------------------------------------------------------------------
// K_h: h = x @ Wt^T + bt -> g_hext (bf16 [k][64])
// 32 rows/CTA; lanes split k 4-ways (fc=lane>>3), combined via 2x shfl_xor.
// No part[] phase, single __syncthreads.
// ---------------------------------------------------------------------------
__global__ void __launch_bounds__(256, 2) k_h(const float* __restrict__ x,
                                              const float* __restrict__ Wt,
                                              const float* __restrict__ bt) {
    __shared__ __align__(16) float xs[32][FD];      // 32 KB
    const int tid = threadIdx.x;
    const int lane = tid & 31, warp = tid >> 5;
    const int cl = lane & 7;          // col within warp's 8
    const int fc = lane >> 3;         // k-quarter 0..3
    const int c = warp * 8 + cl;      // output column 0..63

    float w[64];
    {
        const float4* wr = (const float4*)(Wt + (size_t)c * FD + fc * 64);
#pragma unroll
        for (int j = 0; j < 16; j++) {
            float4 v = wr[j];
            w[4 * j] = v.x; w[4 * j + 1] = v.y; w[4 * j + 2] = v.z; w[4 * j + 3] = v.w;
        }
    }
    const float btc = bt[c];

    const int r0 = blockIdx.x * 32;   // grid 256 covers 8192
    {
        const float4* xsrc = (const float4*)(x + (size_t)r0 * FD);
        float4* xd = (float4*)xs;
#pragma unroll
        for (int j = 0; j < 8; j++) xd[tid + j * 256] = xsrc[tid + j * 256];
    }
    __syncthreads();

#pragma unroll 4
    for (int r = 0; r < 32; r++) {
        const float4* xv = (const float4*)(&xs[r][fc * 64]);
        float p0 = 0.f, p1 = 0.f, p2 = 0.f, p3 = 0.f;
#pragma unroll
        for (int j = 0; j < 16; j += 4) {
            float4 v0 = xv[j], v1 = xv[j + 1], v2 = xv[j + 2], v3 = xv[j + 3];
            p0 += v0.x * w[4 * j + 0] + v0.y * w[4 * j + 1] + v0.z * w[4 * j + 2] + v0.w * w[4 * j + 3];
            p1 += v1.x * w[4 * j + 4] + v1.y * w[4 * j + 5] + v1.z * w[4 * j + 6] + v1.w * w[4 * j + 7];
            p2 += v2.x * w[4 * j + 8] + v2.y * w[4 * j + 9] + v2.z * w[4 * j + 10] + v2.w * w[4 * j + 11];
            p3 += v3.x * w[4 * j + 12] + v3.y * w[4 * j + 13] + v3.z * w[4 * j + 14] + v3.w * w[4 * j + 15];
        }
        float p = (p0 + p1) + (p2 + p3);
        p += __shfl_xor_sync(0xffffffffu, p, 8);
        p += __shfl_xor_sync(0xffffffffu, p, 16);
        if (fc == 0)
            g_hext[(size_t)(r0 + r) * HD + c] = __float2bfloat16(p + btc);
    }
}

// ---------------------------------------------------------------------------
// K_mm: Cp[kq] = adj(0/1 -> bf16) @ h^T (N=64) via mma.sync m16n8k16 bf16
//  - deg computed on ALU from the register-resident adj values (exact),
//    smem-reduced, stored in col 64 -> no 9th n-tile, balanced warps
//  - A: coalesced LDG.128 -> reg bf16 pack -> swizzled STS.64 (R10-validated)
//  - B: 3-stage cp.async ring (512 chunks/tile), nset = cols 0-31 / 32-63
// ---------------------------------------------------------------------------
__global__ void __launch_bounds__(256, 2) k_adj_mm(const int* __restrict__ adj) {
    extern __shared__ __align__(16) char dyn[];
    char* sA = dyn;                                          // 2 x 16384 B
    __nv_bfloat16* sB0 = (__nv_bfloat16*)(dyn + 2 * SA_BYTES);
    __shared__ int sdeg[BM];

    const int tid = threadIdx.x;
    const int warp = tid >> 5, lane = tid & 31;
    const int mtile = blockIdx.x >> 2, kq = blockIdx.x & 3;
    const int rowBase = mtile * BM;
    const int kbase = kq * (NN / KSPLIT);
    const int mgroup = warp & 3;          // 32-row group
    const int nset = warp >> 2;           // 0: cols 0-31, 1: cols 32-63

    if (tid < BM) sdeg[tid] = 0;

    // A producer mapping (coalesced): thread owns chunk (row = tid>>4 + 16j, c16 = tid&15)
    const int arow = tid >> 4;
    const int c16 = tid & 15;
    const int* ap = adj + (size_t)(rowBase + arow) * NN + kbase + c16 * 4;

    float acc[2][4][4];
#pragma unroll
    for (int a = 0; a < 2; a++)
#pragma unroll
        for (int i = 0; i < 4; i++)
            acc[a][i][0] = acc[a][i][1] = acc[a][i][2] = acc[a][i][3] = 0.f;
    int degp[8];
#pragma unroll
    for (int j = 0; j < 8; j++) degp[j] = 0;

    int4 rA[8];
#pragma unroll
    for (int j = 0; j < 8; j++) rA[j] = *(const int4*)(ap + (size_t)(16 * j) * NN);

    const uint32_t sAu = (uint32_t)__cvta_generic_to_shared(sA);
    const uint32_t sBu = (uint32_t)__cvta_generic_to_shared(sB0);
    auto loadB = [&](int stage, int ktg) {
#pragma unroll
        for (int j = 0; j < 2; j++) {
            int i = tid + j * 256;          // 512 chunks of 16B (h 64x64 bf16)
            int r = i >> 3, cc = i & 7;
            cpa16((char*)sB0 + stage * SB_TILE * 2 + (r * SB_STR + cc * 8) * 2,
                  g_hext + (size_t)(ktg * BK + r) * HD + cc * 8);
        }
        asm volatile("cp.async.commit_group;\n");
    };
    loadB(0, kq * NITL + 0);
    loadB(1, kq * NITL + 1);

    const int sts_row_off = (((c16 >> 1) ^ (arow & 7)) * 16) + (c16 & 1) * 8;

    for (int kt = 0; kt < NITL; ++kt) {
        // pack A -> bf16, swizzled STS.64; accumulate deg on ALU
        {
            const uint32_t abase = sAu + (kt & 1) * SA_BYTES;
#pragma unroll
            for (int j = 0; j < 8; j++) {
                int4 v = rA[j];
                degp[j] += v.x + v.y + v.z + v.w;
                uint lo = (uint)v.x * 0x3F80u + (uint)v.y * 0x3F800000u;
                uint hi = (uint)v.z * 0x3F80u + (uint)v.w * 0x3F800000u;
                uint32_t d = abase + (arow + 16 * j) * 128 + sts_row_off;
                asm volatile("st.shared.v2.b32 [%0], {%1, %2};"
                             :: "r"(d), "r"(lo), "r"(hi) : "memory");
            }
        }
        if (kt + 1 < NITL) {
            const int* np = ap + (size_t)(kt + 1) * BK;
#pragma unroll
            for (int j = 0; j < 8; j++) rA[j] = *(const int4*)(np + (size_t)(16 * j) * NN);
        }

        asm volatile("cp.async.wait_group 1;\n");
        __syncthreads();
        if (kt + 2 < NITL) loadB((kt + 2) % 3, kq * NITL + kt + 2);

        const __nv_bfloat16* sB = sB0 + (kt % 3) * SB_TILE;
        const uint32_t sAb = sAu + (kt & 1) * SA_BYTES;

#pragma unroll
        for (int ks = 0; ks < 4; ++ks) {
            uint a[2][4];
#pragma unroll
            for (int mf = 0; mf < 2; mf++) {
                int row = mgroup * 32 + mf * 16 + (lane & 15);
                int chunk = 2 * ks + (lane >> 4);
                uint32_t addr = sAb + row * 128 + ((chunk ^ (lane & 7)) * 16);
                asm volatile("ldmatrix.sync.aligned.m8n8.x4.shared.b16 {%0,%1,%2,%3},[%4];\n"
                             : "=r"(a[mf][0]), "=r"(a[mf][1]), "=r"(a[mf][2]), "=r"(a[mf][3])
                             : "r"(addr));
            }
            const int kk = ks * 16 + (lane & 15);
            uint b[8];
#pragma unroll
            for (int pl = 0; pl < 2; pl++) {
                uint32_t addr = (uint32_t)__cvta_generic_to_shared(
                    &sB[kk * SB_STR + nset * 32 + pl * 16 + ((lane >> 4) << 3)]);
                asm volatile("ldmatrix.sync.aligned.m8n8.x4.trans.shared.b16 {%0,%1,%2,%3},[%4];\n"
                             : "=r"(b[4 * pl]), "=r"(b[4 * pl + 1]),
                               "=r"(b[4 * pl + 2]), "=r"(b[4 * pl + 3])
                             : "r"(addr));
            }
#pragma unroll
            for (int mf = 0; mf < 2; mf++) {
#pragma unroll
                for (int t = 0; t < 4; t++) {
                    asm volatile("mma.sync.aligned.m16n8k16.row.col.f32.bf16.bf16.f32 "
                                 "{%0,%1,%2,%3},{%4,%5,%6,%7},{%8,%9},{%0,%1,%2,%3};\n"
                                 : "+f"(acc[mf][t][0]), "+f"(acc[mf][t][1]),
                                   "+f"(acc[mf][t][2]), "+f"(acc[mf][t][3])
                                 : "r"(a[mf][0]), "r"(a[mf][1]), "r"(a[mf][2]), "r"(a[mf][3]),
                                   "r"(b[2 * t]), "r"(b[2 * t + 1]));
                }
            }
        }
        __syncthreads();
    }

    // deg reduction (16 threads per row)
#pragma unroll
    for (int j = 0; j < 8; j++) atomicAdd(&sdeg[arow + 16 * j], degp[j]);
    __syncthreads();

    float* Cout = g_Cp + (size_t)kq * NN * NTC;
    const int gr = lane >> 2, gc = (lane & 3) * 2;
#pragma unroll
    for (int mf = 0; mf < 2; mf++) {
#pragma unroll
        for (int lt = 0; lt < 4; ++lt) {
            const int gt = nset * 4 + lt;
            size_t base = (size_t)(rowBase + mgroup * 32 + mf * 16 + gr) * NTC + gt * 8 + gc;
            Cout[base] = acc[mf][lt][0];
            Cout[base + 1] = acc[mf][lt][1];
            Cout[base + (size_t)8 * NTC] = acc[mf][lt][2];
            Cout[base + (size_t)8 * NTC + 1] = acc[mf][lt][3];
        }
    }
    if (tid < BM) Cout[(size_t)(rowBase + tid) * NTC + HD] = (float)sdeg[tid];
}

// ---------------------------------------------------------------------------
// K_epi: C = sum of 4 partials; neighbor = C/deg;
//        tf = neighbor @ Wp^T + bp; y = x + tf; LayerNorm(y) -> out.
// ---------------------------------------------------------------------------
__global__ void __launch_bounds__(256) k_epi(const float* __restrict__ x,
                                             const float* __restrict__ Wp,
                                             const float* __restrict__ bp,
                                             const float* __restrict__ gamma,
                                             const float* __restrict__ beta,
                                             float* __restrict__ out) {
    __shared__ __align__(16) float nb[16][HD];
    __shared__ float pwS[8][16], pwQ[8][16];
    __shared__ float muS[16], rsS[16];
    const int row0 = blockIdx.x * 16;
    const int t = threadIdx.x;
    const int warp = t >> 5, lane = t & 31;

#pragma unroll
    for (int j = 0; j < 4; j++) {
        int i = t + j * 256;
        int r = i >> 6, cc = i & 63;
        size_t rb = (size_t)(row0 + r) * NTC;
        float deg = 0.f, v = 0.f;
#pragma unroll
        for (int q = 0; q < KSPLIT; q++) {
            const float* Cq = g_Cp + (size_t)q * NN * NTC;
            deg += Cq[rb + HD];
            v += Cq[rb + cc];
        }
        nb[r][cc] = (deg > 0.5f) ? v / deg : 0.f;
    }
    __syncthreads();

    float tf[16];
    {
        float b = bp[t];
#pragma unroll
        for (int r = 0; r < 16; r++) tf[r] = b;
    }
    const float4* wp4 = (const float4*)(Wp + (size_t)t * HD);
#pragma unroll
    for (int q = 0; q < 16; q++) {
        float4 w = wp4[q];
#pragma unroll
        for (int r = 0; r < 16; r++) {
            float4 nv = *(const float4*)(&nb[r][q * 4]);
            tf[r] += nv.x * w.x + nv.y * w.y + nv.z * w.z + nv.w * w.w;
        }
    }

    float y[16];
#pragma unroll
    for (int r = 0; r < 16; r++) y[r] = x[(size_t)(row0 + r) * FD + t] + tf[r];

#pragma unroll
    for (int r = 0; r < 16; r++) {
        float s = y[r], q = y[r] * y[r];
#pragma unroll
        for (int o = 16; o > 0; o >>= 1) {
            s += __shfl_xor_sync(0xffffffffu, s, o);
            q += __shfl_xor_sync(0xffffffffu, q, o);
        }
        if (lane == 0) { pwS[warp][r] = s; pwQ[warp][r] = q; }
    }
    __syncthreads();
    if (t < 16) {
        float s = 0.f, q = 0.f;
#pragma unroll
        for (int w = 0; w < 8; w++) { s += pwS[w][t]; q += pwQ[w][t]; }
        float mu = s * (1.f / FD);
        float var = q * (1.f / FD) - mu * mu;
        muS[t] = mu;
        rsS[t] = rsqrtf(var + 1e-5f);
    }
    __syncthreads();

    const float g = gamma[t], b = beta[t];
#pragma unroll
    for (int r = 0; r < 16; r++)
        out[(size_t)(row0 + r) * FD + t] = g * (y[r] - muS[r]) * rsS[r] + b;
}

// ---------------------------------------------------------------------------
extern "C" void kernel_launch(void* const* d_in, const int* in_sizes, int n_in,
                              void* d_out, int out_size) {
    const float* x     = (const float*)d_in[0];
    const int*   adj   = (const int*)d_in[1];
    const float* Wt    = (const float*)d_in[2];
    const float* bt    = (const float*)d_in[3];
    // d_in[4] (Wa), d_in[5] (ba): mathematically irrelevant — softmax over
    // row-constant scores collapses to 1/deg regardless of s.
    const float* Wp    = (const float*)d_in[6];
    const float* bp    = (const float*)d_in[7];
    const float* gamma = (const float*)d_in[8];
    const float* beta  = (const float*)d_in[9];
    float* out = (float*)d_out;

    cudaFuncSetAttribute(k_adj_mm, cudaFuncAttributeMaxDynamicSharedMemorySize, SMEM_MM);
    k_h<<<NN / 32, 256>>>(x, Wt, bt);
    k_adj_mm<<<(NN / BM) * KSPLIT, 256, SMEM_MM>>>(adj);
    k_epi<<<NN / 16, 256>>>(x, Wp, bp, gamma, beta, out);
}

// round 13
// speedup vs baseline: 1.7585x; 1.7585x over previous
#include <cuda_runtime.h>
#include <cuda_bf16.h>
#include <cstdint>

#define NN 8192
#define FD 256
#define HD 64
#define HE 80      // h_ext columns (64 h + ones col 64 + 15 zero)
#define NTC 72     // C columns (deg at col 64)
#define BM 128
#define BK 64
#define KSPLIT 4
#define NITL (NN / BK / KSPLIT)   // 32 k-tiles per CTA
#define SB_STR 88                 // bf16 per sB row (conflict-free trans ldmatrix)
#define SB_TILE (BK * SB_STR)     // 5632 bf16 = 11264 B
#define SA_BYTES (BM * 128)       // 16384 B per A stage (bf16, 128B rows)
#define SMEM_MM (2 * SA_BYTES + 3 * SB_TILE * 2)      // 66560
#define SMEM_HMM (2 * SA_BYTES + FD * SB_STR * 2)     // 32768 + 45056 = 77824

// device scratch (static allocation only — no cudaMalloc allowed)
__device__ __align__(16) __nv_bfloat16 g_hext[NN * HE];
__device__ __align__(16) __nv_bfloat16 g_wt[FD * HD];   // Wt^T bf16 [k][c]
__device__ __align__(16) float g_Cp[KSPLIT * NN * NTC];

typedef unsigned int uint;

__device__ __forceinline__ void cpa16(void* dst, const void* src) {
    uint32_t d = (uint32_t)__cvta_generic_to_shared(dst);
    asm volatile("cp.async.cg.shared.global [%0], [%1], 16;\n" :: "r"(d), "l"(src));
}

// ---------------------------------------------------------------------------
// K_w: g_wt[k][c] = bf16(Wt[c][k])  (coalesced reads over k)
// ---------------------------------------------------------------------------
__global__ void __launch_bounds__(256) k_w(const float* __restrict__ Wt) {
    int i = blockIdx.x * 256 + threadIdx.x;   // grid 64 -> 16384 elems
    int c = i >> 8, k = i & 255;
    g_wt[(size_t)k * HD + c] = __float2bfloat16(Wt[(size_t)c * FD + k]);
}

// ---------------------------------------------------------------------------
// K_hmm: h = x @ Wt^T + bt -> g_hext bf16 (80 cols; col 64 = 1, 65-79 = 0)
// Tensor-core clone of the adj mm skeleton: BM=128, 4 k-tiles of 64,
// A = x cvt to bf16 in regs -> swizzled STS.64; B = g_wt loaded once.
// ---------------------------------------------------------------------------
__global__ void __launch_bounds__(256) k_hmm(const float* __restrict__ x,
                                             const float* __restrict__ bt) {
    extern __shared__ __align__(16) char dynh[];
    char* sA = dynh;                                         // 2 x 16384 B
    __nv_bfloat16* sBW = (__nv_bfloat16*)(dynh + 2 * SA_BYTES);  // [256][88]

    const int tid = threadIdx.x;
    const int warp = tid >> 5, lane = tid & 31;
    const int rowBase = blockIdx.x * BM;    // grid 64
    const int mgroup = warp & 3;
    const int nset = warp >> 2;             // 0: cols 0-31, 1: cols 32-63

    const int arow = tid >> 4;
    const int c16 = tid & 15;
    const float* apx = x + (size_t)(rowBase + arow) * FD + c16 * 4;

    // B: all 256 k-rows of Wt^T -> smem (2048 16B chunks)
#pragma unroll
    for (int j = 0; j < 8; j++) {
        int i = tid + j * 256;
        int r = i >> 3, cc = i & 7;
        cpa16((char*)sBW + (r * SB_STR + cc * 8) * 2, g_wt + (size_t)r * HD + cc * 8);
    }
    asm volatile("cp.async.commit_group;\n");

    float acc[2][4][4];
#pragma unroll
    for (int a = 0; a < 2; a++)
#pragma unroll
        for (int i = 0; i < 4; i++)
            acc[a][i][0] = acc[a][i][1] = acc[a][i][2] = acc[a][i][3] = 0.f;

    float4 rX[8];
#pragma unroll
    for (int j = 0; j < 8; j++) rX[j] = *(const float4*)(apx + (size_t)(16 * j) * FD);

    const uint32_t sAu = (uint32_t)__cvta_generic_to_shared(sA);
    const int sts_row_off = (((c16 >> 1) ^ (arow & 7)) * 16) + (c16 & 1) * 8;

#pragma unroll
    for (int kt = 0; kt < 4; ++kt) {
        {
            const uint32_t abase = sAu + (kt & 1) * SA_BYTES;
#pragma unroll
            for (int j = 0; j < 8; j++) {
                __nv_bfloat162 h0 = __floats2bfloat162_rn(rX[j].x, rX[j].y);
                __nv_bfloat162 h1 = __floats2bfloat162_rn(rX[j].z, rX[j].w);
                uint lo = *reinterpret_cast<uint*>(&h0);
                uint hi = *reinterpret_cast<uint*>(&h1);
                uint32_t d = abase + (arow + 16 * j) * 128 + sts_row_off;
                asm volatile("st.shared.v2.b32 [%0], {%1, %2};"
                             :: "r"(d), "r"(lo), "r"(hi) : "memory");
            }
        }
        if (kt < 3) {
#pragma unroll
            for (int j = 0; j < 8; j++)
                rX[j] = *(const float4*)(apx + (kt + 1) * 64 + (size_t)(16 * j) * FD);
        }
        if (kt == 0) asm volatile("cp.async.wait_group 0;\n");
        __syncthreads();

        const uint32_t sAb = sAu + (kt & 1) * SA_BYTES;
#pragma unroll
        for (int ks = 0; ks < 4; ++ks) {
            uint a[2][4];
#pragma unroll
            for (int mf = 0; mf < 2; mf++) {
                int row = mgroup * 32 + mf * 16 + (lane & 15);
                int chunk = 2 * ks + (lane >> 4);
                uint32_t addr = sAb + row * 128 + ((chunk ^ (lane & 7)) * 16);
                asm volatile("ldmatrix.sync.aligned.m8n8.x4.shared.b16 {%0,%1,%2,%3},[%4];\n"
                             : "=r"(a[mf][0]), "=r"(a[mf][1]), "=r"(a[mf][2]), "=r"(a[mf][3])
                             : "r"(addr));
            }
            const int kk = kt * 64 + ks * 16 + (lane & 15);
            uint b[8];
#pragma unroll
            for (int pl = 0; pl < 2; pl++) {
                uint32_t addr = (uint32_t)__cvta_generic_to_shared(
                    &sBW[kk * SB_STR + nset * 32 + pl * 16 + ((lane >> 4) << 3)]);
                asm volatile("ldmatrix.sync.aligned.m8n8.x4.trans.shared.b16 {%0,%1,%2,%3},[%4];\n"
                             : "=r"(b[4 * pl]), "=r"(b[4 * pl + 1]),
                               "=r"(b[4 * pl + 2]), "=r"(b[4 * pl + 3])
                             : "r"(addr));
            }
#pragma unroll
            for (int mf = 0; mf < 2; mf++) {
#pragma unroll
                for (int t = 0; t < 4; t++) {
                    asm volatile("mma.sync.aligned.m16n8k16.row.col.f32.bf16.bf16.f32 "
                                 "{%0,%1,%2,%3},{%4,%5,%6,%7},{%8,%9},{%0,%1,%2,%3};\n"
                                 : "+f"(acc[mf][t][0]), "+f"(acc[mf][t][1]),
                                   "+f"(acc[mf][t][2]), "+f"(acc[mf][t][3])
                                 : "r"(a[mf][0]), "r"(a[mf][1]), "r"(a[mf][2]), "r"(a[mf][3]),
                                   "r"(b[2 * t]), "r"(b[2 * t + 1]));
                }
            }
        }
        __syncthreads();
    }

    // epilogue: add bias, cvt bf16, store h + pad columns
    const int gr = lane >> 2, gc = (lane & 3) * 2;
#pragma unroll
    for (int t = 0; t < 4; t++) {
        const int c0 = nset * 32 + t * 8 + gc;
        const float b0 = bt[c0], b1 = bt[c0 + 1];
#pragma unroll
        for (int mf = 0; mf < 2; mf++) {
            int row = rowBase + mgroup * 32 + mf * 16 + gr;
            __nv_bfloat162 v0 = __floats2bfloat162_rn(acc[mf][t][0] + b0, acc[mf][t][1] + b1);
            __nv_bfloat162 v1 = __floats2bfloat162_rn(acc[mf][t][2] + b0, acc[mf][t][3] + b1);
            *reinterpret_cast<__nv_bfloat162*>(&g_hext[(size_t)row * HE + c0]) = v0;
            *reinterpret_cast<__nv_bfloat162*>(&g_hext[(size_t)(row + 8) * HE + c0]) = v1;
        }
    }
    {   // cols 64..79: ones column (deg) + zeros; 16B per thread
        int row = rowBase + (tid >> 1), half = tid & 1;
        uint4 v = (half == 0) ? make_uint4(0x00003F80u, 0u, 0u, 0u)
                              : make_uint4(0u, 0u, 0u, 0u);
        *reinterpret_cast<uint4*>(&g_hext[(size_t)row * HE + 64 + half * 8]) = v;
    }
}

// ---------------------------------------------------------------------------
// K_mm: Cp[kq] = adj(0/1 -> bf16) @ h_ext (N=72 incl deg col) — R10-proven.
// ---------------------------------------------------------------------------
__device__ __forceinline__ void loadB(__nv_bfloat16* sB, int ktg, int tid) {
#pragma unroll
    for (int j = 0; j < 3; j++) {
        int i = tid + j * 256;          // 640 chunks of 16B (h_ext 64x80 bf16)
        if (i < 640) {
            int r = i / 10, cc = i % 10;
            cpa16(sB + r * SB_STR + cc * 8, g_hext + (size_t)(ktg * BK + r) * HE + cc * 8);
        }
    }
    asm volatile("cp.async.commit_group;\n");
}

__global__ void __launch_bounds__(256, 2) k_adj_mm(const int* __restrict__ adj) {
    extern __shared__ __align__(16) char dyn[];
    char* sA = dyn;                                          // 2 x 16384 B
    __nv_bfloat16* sB0 = (__nv_bfloat16*)(dyn + 2 * SA_BYTES);

    const int tid = threadIdx.x;
    const int warp = tid >> 5, lane = tid & 31;
    const int mtile = blockIdx.x >> 2, kq = blockIdx.x & 3;
    const int rowBase = mtile * BM;
    const int kbase = kq * (NN / KSPLIT);
    const int mgroup = warp & 3;
    const int nset = warp >> 2;           // 0: tiles 0-4, 1: tiles 5-8

    const int arow = tid >> 4;
    const int c16 = tid & 15;
    const int* ap = adj + (size_t)(rowBase + arow) * NN + kbase + c16 * 4;

    float acc[2][5][4];
#pragma unroll
    for (int a = 0; a < 2; a++)
#pragma unroll
        for (int i = 0; i < 5; i++)
            acc[a][i][0] = acc[a][i][1] = acc[a][i][2] = acc[a][i][3] = 0.f;

    int4 rA[8];
#pragma unroll
    for (int j = 0; j < 8; j++) rA[j] = *(const int4*)(ap + (size_t)(16 * j) * NN);

    loadB(sB0 + 0 * SB_TILE, kq * NITL + 0, tid);
    loadB(sB0 + 1 * SB_TILE, kq * NITL + 1, tid);

    const uint32_t sAu = (uint32_t)__cvta_generic_to_shared(sA);
    const int sts_row_off = (((c16 >> 1) ^ (arow & 7)) * 16) + (c16 & 1) * 8;

    for (int kt = 0; kt < NITL; ++kt) {
        {
            const uint32_t abase = sAu + (kt & 1) * SA_BYTES;
#pragma unroll
            for (int j = 0; j < 8; j++) {
                int4 v = rA[j];
                uint lo = (uint)v.x * 0x3F80u + (uint)v.y * 0x3F800000u;
                uint hi = (uint)v.z * 0x3F80u + (uint)v.w * 0x3F800000u;
                uint32_t d = abase + (arow + 16 * j) * 128 + sts_row_off;
                asm volatile("st.shared.v2.b32 [%0], {%1, %2};"
                             :: "r"(d), "r"(lo), "r"(hi) : "memory");
            }
        }
        if (kt + 1 < NITL) {
            const int* np = ap + (size_t)(kt + 1) * BK;
#pragma unroll
            for (int j = 0; j < 8; j++) rA[j] = *(const int4*)(np + (size_t)(16 * j) * NN);
        }

        asm volatile("cp.async.wait_group 1;\n");
        __syncthreads();
        if (kt + 2 < NITL) loadB(sB0 + ((kt + 2) % 3) * SB_TILE, kq * NITL + kt + 2, tid);

        const __nv_bfloat16* sB = sB0 + (kt % 3) * SB_TILE;
        const uint32_t sAb = sAu + (kt & 1) * SA_BYTES;

#pragma unroll
        for (int ks = 0; ks < 4; ++ks) {
            uint a[2][4];
#pragma unroll
            for (int mf = 0; mf < 2; mf++) {
                int row = mgroup * 32 + mf * 16 + (lane & 15);
                int chunk = 2 * ks + (lane >> 4);
                uint32_t addr = sAb + row * 128 + ((chunk ^ (lane & 7)) * 16);
                asm volatile("ldmatrix.sync.aligned.m8n8.x4.shared.b16 {%0,%1,%2,%3},[%4];\n"
                             : "=r"(a[mf][0]), "=r"(a[mf][1]), "=r"(a[mf][2]), "=r"(a[mf][3])
                             : "r"(addr));
            }
            const int kk = ks * 16 + (lane & 15);
            if (nset == 0) {
                uint b[10];
#pragma unroll
                for (int pl = 0; pl < 2; pl++) {
                    uint32_t addr = (uint32_t)__cvta_generic_to_shared(
                        &sB[kk * SB_STR + pl * 16 + ((lane >> 4) << 3)]);
                    asm volatile("ldmatrix.sync.aligned.m8n8.x4.trans.shared.b16 {%0,%1,%2,%3},[%4];\n"
                                 : "=r"(b[4 * pl]), "=r"(b[4 * pl + 1]),
                                   "=r"(b[4 * pl + 2]), "=r"(b[4 * pl + 3])
                                 : "r"(addr));
                }
                {
                    uint32_t addr = (uint32_t)__cvta_generic_to_shared(&sB[kk * SB_STR + 32]);
                    asm volatile("ldmatrix.sync.aligned.m8n8.x2.trans.shared.b16 {%0,%1},[%2];\n"
                                 : "=r"(b[8]), "=r"(b[9]) : "r"(addr));
                }
#pragma unroll
                for (int mf = 0; mf < 2; mf++) {
#pragma unroll
                    for (int t = 0; t < 5; t++) {
                        asm volatile("mma.sync.aligned.m16n8k16.row.col.f32.bf16.bf16.f32 "
                                     "{%0,%1,%2,%3},{%4,%5,%6,%7},{%8,%9},{%0,%1,%2,%3};\n"
                                     : "+f"(acc[mf][t][0]), "+f"(acc[mf][t][1]),
                                       "+f"(acc[mf][t][2]), "+f"(acc[mf][t][3])
                                     : "r"(a[mf][0]), "r"(a[mf][1]), "r"(a[mf][2]), "r"(a[mf][3]),
                                       "r"(b[2 * t]), "r"(b[2 * t + 1]));
                    }
                }
            } else {
                uint b[8];
#pragma unroll
                for (int pl = 0; pl < 2; pl++) {
                    uint32_t addr = (uint32_t)__cvta_generic_to_shared(
                        &sB[kk * SB_STR + 40 + pl * 16 + ((lane >> 4) << 3)]);
                    asm volatile("ldmatrix.sync.aligned.m8n8.x4.trans.shared.b16 {%0,%1,%2,%3},[%4];\n"
                                 : "=r"(b[4 * pl]), "=r"(b[4 * pl + 1]),
                                   "=r"(b[4 * pl + 2]), "=r"(b[4 * pl + 3])
                                 : "r"(addr));
                }
#pragma unroll
                for (int mf = 0; mf < 2; mf++) {
#pragma unroll
                    for (int t = 0; t < 4; t++) {
                        asm volatile("mma.sync.aligned.m16n8k16.row.col.f32.bf16.bf16.f32 "
                                     "{%0,%1,%2,%3},{%4,%5,%6,%7},{%8,%9},{%0,%1,%2,%3};\n"
                                     : "+f"(acc[mf][t][0]), "+f"(acc[mf][t][1]),
                                       "+f"(acc[mf][t][2]), "+f"(acc[mf][t][3])
                                     : "r"(a[mf][0]), "r"(a[mf][1]), "r"(a[mf][2]), "r"(a[mf][3]),
                                       "r"(b[2 * t]), "r"(b[2 * t + 1]));
                    }
                }
            }
        }
    }

    float* Cout = g_Cp + (size_t)kq * NN * NTC;
    const int gr = lane >> 2, gc = (lane & 3) * 2;
    const int ntiles = (nset == 0) ? 5 : 4;
#pragma unroll
    for (int mf = 0; mf < 2; mf++) {
#pragma unroll
        for (int lt = 0; lt < 5; ++lt) {
            if (lt >= ntiles) break;
            const int gt = (nset == 0) ? lt : (5 + lt);
            size_t base = (size_t)(rowBase + mgroup * 32 + mf * 16 + gr) * NTC + gt * 8 + gc;
            Cout[base] = acc[mf][lt][0];
            Cout[base + 1] = acc[mf][lt][1];
            Cout[base + (size_t)8 * NTC] = acc[mf][lt][2];
            Cout[base + (size_t)8 * NTC + 1] = acc[mf][lt][3];
        }
    }
}

// ---------------------------------------------------------------------------
// K_epi: C = sum of 4 partials; neighbor = C/deg;
//        tf = neighbor @ Wp^T + bp; y = x + tf; LayerNorm(y) -> out.
// ---------------------------------------------------------------------------
__global__ void __launch_bounds__(256) k_epi(const float* __restrict__ x,
                                             const float* __restrict__ Wp,
                                             const float* __restrict__ bp,
                                             const float* __restrict__ gamma,
                                             const float* __restrict__ beta,
                                             float* __restrict__ out) {
    __shared__ __align__(16) float nb[16][HD];
    __shared__ float pwS[8][16], pwQ[8][16];
    __shared__ float muS[16], rsS[16];
    const int row0 = blockIdx.x * 16;
    const int t = threadIdx.x;
    const int warp = t >> 5, lane = t & 31;

#pragma unroll
    for (int j = 0; j < 4; j++) {
        int i = t + j * 256;
        int r = i >> 6, cc = i & 63;
        size_t rb = (size_t)(row0 + r) * NTC;
        float deg = 0.f, v = 0.f;
#pragma unroll
        for (int q = 0; q < KSPLIT; q++) {
            const float* Cq = g_Cp + (size_t)q * NN * NTC;
            deg += Cq[rb + HD];
            v += Cq[rb + cc];
        }
        nb[r][cc] = (deg > 0.5f) ? v / deg : 0.f;
    }
    __syncthreads();

    float tf[16];
    {
        float b = bp[t];
#pragma unroll
        for (int r = 0; r < 16; r++) tf[r] = b;
    }
    const float4* wp4 = (const float4*)(Wp + (size_t)t * HD);
#pragma unroll
    for (int q = 0; q < 16; q++) {
        float4 w = wp4[q];
#pragma unroll
        for (int r = 0; r < 16; r++) {
            float4 nv = *(const float4*)(&nb[r][q * 4]);
            tf[r] += nv.x * w.x + nv.y * w.y + nv.z * w.z + nv.w * w.w;
        }
    }

    float y[16];
#pragma unroll
    for (int r = 0; r < 16; r++) y[r] = x[(size_t)(row0 + r) * FD + t] + tf[r];

#pragma unroll
    for (int r = 0; r < 16; r++) {
        float s = y[r], q = y[r] * y[r];
#pragma unroll
        for (int o = 16; o > 0; o >>= 1) {
            s += __shfl_xor_sync(0xffffffffu, s, o);
            q += __shfl_xor_sync(0xffffffffu, q, o);
        }
        if (lane == 0) { pwS[warp][r] = s; pwQ[warp][r] = q; }
    }
    __syncthreads();
    if (t < 16) {
        float s = 0.f, q = 0.f;
#pragma unroll
        for (int w = 0; w < 8; w++) { s += pwS[w][t]; q += pwQ[w][t]; }
        float mu = s * (1.f / FD);
        float var = q * (1.f / FD) - mu * mu;
        muS[t] = mu;
        rsS[t] = rsqrtf(var + 1e-5f);
    }
    __syncthreads();

    const float g = gamma[t], b = beta[t];
#pragma unroll
    for (int r = 0; r < 16; r++)
        out[(size_t)(row0 + r) * FD + t] = g * (y[r] - muS[r]) * rsS[r] + b;
}

// ---------------------------------------------------------------------------
extern "C" void kernel_launch(void* const* d_in, const int* in_sizes, int n_in,
                              void* d_out, int out_size) {
    const float* x     = (const float*)d_in[0];
    const int*   adj   = (const int*)d_in[1];
    const float* Wt    = (const float*)d_in[2];
    const float* bt    = (const float*)d_in[3];
    // d_in[4] (Wa), d_in[5] (ba): mathematically irrelevant — softmax over
    // row-constant scores collapses to 1/deg regardless of s.
    const float* Wp    = (const float*)d_in[6];
    const float* bp    = (const float*)d_in[7];
    const float* gamma = (const float*)d_in[8];
    const float* beta  = (const float*)d_in[9];
    float* out = (float*)d_out;

    cudaFuncSetAttribute(k_adj_mm, cudaFuncAttributeMaxDynamicSharedMemorySize, SMEM_MM);
    cudaFuncSetAttribute(k_hmm, cudaFuncAttributeMaxDynamicSharedMemorySize, SMEM_HMM);
    k_w<<<64, 256>>>(Wt);
    k_hmm<<<NN / BM, 256, SMEM_HMM>>>(x, bt);
    k_adj_mm<<<(NN / BM) * KSPLIT, 256, SMEM_MM>>>(adj);
    k_epi<<<NN / 16, 256>>>(x, Wp, bp, gamma, beta, out);
}

// round 16
// speedup vs baseline: 1.8078x; 1.0281x over previous
#include <cuda_runtime.h>
#include <cuda_bf16.h>
#include <cstdint>

#define NN 8192
#define FD 256
#define HD 64
#define HE 80      // h_ext columns (64 h + ones col 64 + 15 zero)
#define NTC 72     // C columns (deg at col 64)
#define BM 128
#define BK 64
#define KSPLIT 4
#define NITL (NN / BK / KSPLIT)   // 32 k-tiles per CTA
#define SB_STR 88                 // bf16 per sB row (conflict-free trans ldmatrix)
#define SB_TILE (BK * SB_STR)     // 5632 bf16 = 11264 B
#define SA_BYTES (BM * 128)       // 16384 B per A stage (bf16, 128B rows)
#define SMEM_MM (2 * SA_BYTES + 3 * SB_TILE * 2)      // 66560
#define SMEM_HMM (2 * SA_BYTES + FD * SB_STR * 2)     // 77824
#define SMEM_EPI (16 * 257 * 16)                      // 65792 (Wp chunk-major)

// device scratch (static allocation only — no cudaMalloc allowed)
__device__ __align__(16) __nv_bfloat16 g_hext[NN * HE];
__device__ __align__(16) __nv_bfloat16 g_wt[FD * HD];   // Wt^T bf16 [k][c]
__device__ __align__(16) float g_Cp[KSPLIT * NN * NTC];

typedef unsigned int uint;

__device__ __forceinline__ void cpa16(void* dst, const void* src) {
    uint32_t d = (uint32_t)__cvta_generic_to_shared(dst);
    asm volatile("cp.async.cg.shared.global [%0], [%1], 16;\n" :: "r"(d), "l"(src));
}

// ---------------------------------------------------------------------------
// K_w: g_wt[k][c] = bf16(Wt[c][k])  (coalesced reads over k)
// ---------------------------------------------------------------------------
__global__ void __launch_bounds__(256) k_w(const float* __restrict__ Wt) {
    int i = blockIdx.x * 256 + threadIdx.x;   // grid 64 -> 16384 elems
    int c = i >> 8, k = i & 255;
    g_wt[(size_t)k * HD + c] = __float2bfloat16(Wt[(size_t)c * FD + k]);
}

// ---------------------------------------------------------------------------
// K_hmm: h = x @ Wt^T + bt -> g_hext bf16 (80 cols; col 64 = 1, 65-79 = 0)
// ---------------------------------------------------------------------------
__global__ void __launch_bounds__(256) k_hmm(const float* __restrict__ x,
                                             const float* __restrict__ bt) {
    extern __shared__ __align__(16) char dynh[];
    char* sA = dynh;                                         // 2 x 16384 B
    __nv_bfloat16* sBW = (__nv_bfloat16*)(dynh + 2 * SA_BYTES);  // [256][88]

    const int tid = threadIdx.x;
    const int warp = tid >> 5, lane = tid & 31;
    const int rowBase = blockIdx.x * BM;    // grid 64
    const int mgroup = warp & 3;
    const int nset = warp >> 2;             // 0: cols 0-31, 1: cols 32-63

    const int arow = tid >> 4;
    const int c16 = tid & 15;
    const float* apx = x + (size_t)(rowBase + arow) * FD + c16 * 4;

#pragma unroll
    for (int j = 0; j < 8; j++) {
        int i = tid + j * 256;
        int r = i >> 3, cc = i & 7;
        cpa16((char*)sBW + (r * SB_STR + cc * 8) * 2, g_wt + (size_t)r * HD + cc * 8);
    }
    asm volatile("cp.async.commit_group;\n");

    float acc[2][4][4];
#pragma unroll
    for (int a = 0; a < 2; a++)
#pragma unroll
        for (int i = 0; i < 4; i++)
            acc[a][i][0] = acc[a][i][1] = acc[a][i][2] = acc[a][i][3] = 0.f;

    float4 rX[8];
#pragma unroll
    for (int j = 0; j < 8; j++) rX[j] = *(const float4*)(apx + (size_t)(16 * j) * FD);

    const uint32_t sAu = (uint32_t)__cvta_generic_to_shared(sA);
    const int sts_row_off = (((c16 >> 1) ^ (arow & 7)) * 16) + (c16 & 1) * 8;

#pragma unroll
    for (int kt = 0; kt < 4; ++kt) {
        {
            const uint32_t abase = sAu + (kt & 1) * SA_BYTES;
#pragma unroll
            for (int j = 0; j < 8; j++) {
                __nv_bfloat162 h0 = __floats2bfloat162_rn(rX[j].x, rX[j].y);
                __nv_bfloat162 h1 = __floats2bfloat162_rn(rX[j].z, rX[j].w);
                uint lo = *reinterpret_cast<uint*>(&h0);
                uint hi = *reinterpret_cast<uint*>(&h1);
                uint32_t d = abase + (arow + 16 * j) * 128 + sts_row_off;
                asm volatile("st.shared.v2.b32 [%0], {%1, %2};"
                             :: "r"(d), "r"(lo), "r"(hi) : "memory");
            }
        }
        if (kt < 3) {
#pragma unroll
            for (int j = 0; j < 8; j++)
                rX[j] = *(const float4*)(apx + (kt + 1) * 64 + (size_t)(16 * j) * FD);
        }
        if (kt == 0) asm volatile("cp.async.wait_group 0;\n");
        __syncthreads();

        const uint32_t sAb = sAu + (kt & 1) * SA_BYTES;
#pragma unroll
        for (int ks = 0; ks < 4; ++ks) {
            uint a[2][4];
#pragma unroll
            for (int mf = 0; mf < 2; mf++) {
                int row = mgroup * 32 + mf * 16 + (lane & 15);
                int chunk = 2 * ks + (lane >> 4);
                uint32_t addr = sAb + row * 128 + ((chunk ^ (lane & 7)) * 16);
                asm volatile("ldmatrix.sync.aligned.m8n8.x4.shared.b16 {%0,%1,%2,%3},[%4];\n"
                             : "=r"(a[mf][0]), "=r"(a[mf][1]), "=r"(a[mf][2]), "=r"(a[mf][3])
                             : "r"(addr));
            }
            const int kk = kt * 64 + ks * 16 + (lane & 15);
            uint b[8];
#pragma unroll
            for (int pl = 0; pl < 2; pl++) {
                uint32_t addr = (uint32_t)__cvta_generic_to_shared(
                    &sBW[kk * SB_STR + nset * 32 + pl * 16 + ((lane >> 4) << 3)]);
                asm volatile("ldmatrix.sync.aligned.m8n8.x4.trans.shared.b16 {%0,%1,%2,%3},[%4];\n"
                             : "=r"(b[4 * pl]), "=r"(b[4 * pl + 1]),
                               "=r"(b[4 * pl + 2]), "=r"(b[4 * pl + 3])
                             : "r"(addr));
            }
#pragma unroll
            for (int mf = 0; mf < 2; mf++) {
#pragma unroll
                for (int t = 0; t < 4; t++) {
                    asm volatile("mma.sync.aligned.m16n8k16.row.col.f32.bf16.bf16.f32 "
                                 "{%0,%1,%2,%3},{%4,%5,%6,%7},{%8,%9},{%0,%1,%2,%3};\n"
                                 : "+f"(acc[mf][t][0]), "+f"(acc[mf][t][1]),
                                   "+f"(acc[mf][t][2]), "+f"(acc[mf][t][3])
                                 : "r"(a[mf][0]), "r"(a[mf][1]), "r"(a[mf][2]), "r"(a[mf][3]),
                                   "r"(b[2 * t]), "r"(b[2 * t + 1]));
                }
            }
        }
        __syncthreads();
    }

    const int gr = lane >> 2, gc = (lane & 3) * 2;
#pragma unroll
    for (int t = 0; t < 4; t++) {
        const int c0 = nset * 32 + t * 8 + gc;
        const float b0 = bt[c0], b1 = bt[c0 + 1];
#pragma unroll
        for (int mf = 0; mf < 2; mf++) {
            int row = rowBase + mgroup * 32 + mf * 16 + gr;
            __nv_bfloat162 v0 = __floats2bfloat162_rn(acc[mf][t][0] + b0, acc[mf][t][1] + b1);
            __nv_bfloat162 v1 = __floats2bfloat162_rn(acc[mf][t][2] + b0, acc[mf][t][3] + b1);
            *reinterpret_cast<__nv_bfloat162*>(&g_hext[(size_t)row * HE + c0]) = v0;
            *reinterpret_cast<__nv_bfloat162*>(&g_hext[(size_t)(row + 8) * HE + c0]) = v1;
        }
    }
    {
        int row = rowBase + (tid >> 1), half = tid & 1;
        uint4 v = (half == 0) ? make_uint4(0x00003F80u, 0u, 0u, 0u)
                              : make_uint4(0u, 0u, 0u, 0u);
        *reinterpret_cast<uint4*>(&g_hext[(size_t)row * HE + 64 + half * 8]) = v;
    }
}

// ---------------------------------------------------------------------------
// K_mm: Cp[kq] = adj(0/1 -> bf16) @ h_ext (N=72 incl deg col) — R10-proven.
// ---------------------------------------------------------------------------
__device__ __forceinline__ void loadB(__nv_bfloat16* sB, int ktg, int tid) {
#pragma unroll
    for (int j = 0; j < 3; j++) {
        int i = tid + j * 256;
        if (i < 640) {
            int r = i / 10, cc = i % 10;
            cpa16(sB + r * SB_STR + cc * 8, g_hext + (size_t)(ktg * BK + r) * HE + cc * 8);
        }
    }
    asm volatile("cp.async.commit_group;\n");
}

__global__ void __launch_bounds__(256, 2) k_adj_mm(const int* __restrict__ adj) {
    extern __shared__ __align__(16) char dyn[];
    char* sA = dyn;
    __nv_bfloat16* sB0 = (__nv_bfloat16*)(dyn + 2 * SA_BYTES);

    const int tid = threadIdx.x;
    const int warp = tid >> 5, lane = tid & 31;
    const int mtile = blockIdx.x >> 2, kq = blockIdx.x & 3;
    const int rowBase = mtile * BM;
    const int kbase = kq * (NN / KSPLIT);
    const int mgroup = warp & 3;
    const int nset = warp >> 2;

    const int arow = tid >> 4;
    const int c16 = tid & 15;
    const int* ap = adj + (size_t)(rowBase + arow) * NN + kbase + c16 * 4;

    float acc[2][5][4];
#pragma unroll
    for (int a = 0; a < 2; a++)
#pragma unroll
        for (int i = 0; i < 5; i++)
            acc[a][i][0] = acc[a][i][1] = acc[a][i][2] = acc[a][i][3] = 0.f;

    int4 rA[8];
#pragma unroll
    for (int j = 0; j < 8; j++) rA[j] = *(const int4*)(ap + (size_t)(16 * j) * NN);

    loadB(sB0 + 0 * SB_TILE, kq * NITL + 0, tid);
    loadB(sB0 + 1 * SB_TILE, kq * NITL + 1, tid);

    const uint32_t sAu = (uint32_t)__cvta_generic_to_shared(sA);
    const int sts_row_off = (((c16 >> 1) ^ (arow & 7)) * 16) + (c16 & 1) * 8;

    for (int kt = 0; kt < NITL; ++kt) {
        {
            const uint32_t abase = sAu + (kt & 1) * SA_BYTES;
#pragma unroll
            for (int j = 0; j < 8; j++) {
                int4 v = rA[j];
                uint lo = (uint)v.x * 0x3F80u + (uint)v.y * 0x3F800000u;
                uint hi = (uint)v.z * 0x3F80u + (uint)v.w * 0x3F800000u;
                uint32_t d = abase + (arow + 16 * j) * 128 + sts_row_off;
                asm volatile("st.shared.v2.b32 [%0], {%1, %2};"
                             :: "r"(d), "r"(lo), "r"(hi) : "memory");
            }
        }
        if (kt + 1 < NITL) {
            const int* np = ap + (size_t)(kt + 1) * BK;
#pragma unroll
            for (int j = 0; j < 8; j++) rA[j] = *(const int4*)(np + (size_t)(16 * j) * NN);
        }

        asm volatile("cp.async.wait_group 1;\n");
        __syncthreads();
        if (kt + 2 < NITL) loadB(sB0 + ((kt + 2) % 3) * SB_TILE, kq * NITL + kt + 2, tid);

        const __nv_bfloat16* sB = sB0 + (kt % 3) * SB_TILE;
        const uint32_t sAb = sAu + (kt & 1) * SA_BYTES;

#pragma unroll
        for (int ks = 0; ks < 4; ++ks) {
            uint a[2][4];
#pragma unroll
            for (int mf = 0; mf < 2; mf++) {
                int row = mgroup * 32 + mf * 16 + (lane & 15);
                int chunk = 2 * ks + (lane >> 4);
                uint32_t addr = sAb + row * 128 + ((chunk ^ (lane & 7)) * 16);
                asm volatile("ldmatrix.sync.aligned.m8n8.x4.shared.b16 {%0,%1,%2,%3},[%4];\n"
                             : "=r"(a[mf][0]), "=r"(a[mf][1]), "=r"(a[mf][2]), "=r"(a[mf][3])
                             : "r"(addr));
            }
            const int kk = ks * 16 + (lane & 15);
            if (nset == 0) {
                uint b[10];
#pragma unroll
                for (int pl = 0; pl < 2; pl++) {
                    uint32_t addr = (uint32_t)__cvta_generic_to_shared(
                        &sB[kk * SB_STR + pl * 16 + ((lane >> 4) << 3)]);
                    asm volatile("ldmatrix.sync.aligned.m8n8.x4.trans.shared.b16 {%0,%1,%2,%3},[%4];\n"
                                 : "=r"(b[4 * pl]), "=r"(b[4 * pl + 1]),
                                   "=r"(b[4 * pl + 2]), "=r"(b[4 * pl + 3])
                                 : "r"(addr));
                }
                {
                    uint32_t addr = (uint32_t)__cvta_generic_to_shared(&sB[kk * SB_STR + 32]);
                    asm volatile("ldmatrix.sync.aligned.m8n8.x2.trans.shared.b16 {%0,%1},[%2];\n"
                                 : "=r"(b[8]), "=r"(b[9]) : "r"(addr));
                }
#pragma unroll
                for (int mf = 0; mf < 2; mf++) {
#pragma unroll
                    for (int t = 0; t < 5; t++) {
                        asm volatile("mma.sync.aligned.m16n8k16.row.col.f32.bf16.bf16.f32 "
                                     "{%0,%1,%2,%3},{%4,%5,%6,%7},{%8,%9},{%0,%1,%2,%3};\n"
                                     : "+f"(acc[mf][t][0]), "+f"(acc[mf][t][1]),
                                       "+f"(acc[mf][t][2]), "+f"(acc[mf][t][3])
                                     : "r"(a[mf][0]), "r"(a[mf][1]), "r"(a[mf][2]), "r"(a[mf][3]),
                                       "r"(b[2 * t]), "r"(b[2 * t + 1]));
                    }
                }
            } else {
                uint b[8];
#pragma unroll
                for (int pl = 0; pl < 2; pl++) {
                    uint32_t addr = (uint32_t)__cvta_generic_to_shared(
                        &sB[kk * SB_STR + 40 + pl * 16 + ((lane >> 4) << 3)]);
                    asm volatile("ldmatrix.sync.aligned.m8n8.x4.trans.shared.b16 {%0,%1,%2,%3},[%4];\n"
                                 : "=r"(b[4 * pl]), "=r"(b[4 * pl + 1]),
                                   "=r"(b[4 * pl + 2]), "=r"(b[4 * pl + 3])
                                 : "r"(addr));
                }
#pragma unroll
                for (int mf = 0; mf < 2; mf++) {
#pragma unroll
                    for (int t = 0; t < 4; t++) {
                        asm volatile("mma.sync.aligned.m16n8k16.row.col.f32.bf16.bf16.f32 "
                                     "{%0,%1,%2,%3},{%4,%5,%6,%7},{%8,%9},{%0,%1,%2,%3};\n"
                                     : "+f"(acc[mf][t][0]), "+f"(acc[mf][t][1]),
                                       "+f"(acc[mf][t][2]), "+f"(acc[mf][t][3])
                                     : "r"(a[mf][0]), "r"(a[mf][1]), "r"(a[mf][2]), "r"(a[mf][3]),
                                       "r"(b[2 * t]), "r"(b[2 * t + 1]));
                    }
                }
            }
        }
    }

    float* Cout = g_Cp + (size_t)kq * NN * NTC;
    const int gr = lane >> 2, gc = (lane & 3) * 2;
    const int ntiles = (nset == 0) ? 5 : 4;
#pragma unroll
    for (int mf = 0; mf < 2; mf++) {
#pragma unroll
        for (int lt = 0; lt < 5; ++lt) {
            if (lt >= ntiles) break;
            const int gt = (nset == 0) ? lt : (5 + lt);
            size_t base = (size_t)(rowBase + mgroup * 32 + mf * 16 + gr) * NTC + gt * 8 + gc;
            Cout[base] = acc[mf][lt][0];
            Cout[base + 1] = acc[mf][lt][1];
            Cout[base + (size_t)8 * NTC] = acc[mf][lt][2];
            Cout[base + (size_t)8 * NTC + 1] = acc[mf][lt][3];
        }
    }
}

// ---------------------------------------------------------------------------
// K_epi: 16 rows per CTA. Wp staged in smem CHUNK-MAJOR (sw4[q][t], pad 257)
//        -> coalesced fill, conflict-free LDS.128 reads (fixes nL=32 LDG).
// ---------------------------------------------------------------------------
__global__ void __launch_bounds__(256) k_epi(const float* __restrict__ x,
                                             const float* __restrict__ Wp,
                                             const float* __restrict__ bp,
                                             const float* __restrict__ gamma,
                                             const float* __restrict__ beta,
                                             float* __restrict__ out) {
    extern __shared__ __align__(16) float4 sw4[];   // [16][257]
    __shared__ __align__(16) float nb[16][HD];
    __shared__ float pwS[8][16], pwQ[8][16];
    __shared__ float muS[16], rsS[16];
    const int row0 = blockIdx.x * 16;
    const int t = threadIdx.x;
    const int warp = t >> 5, lane = t & 31;

    // fill Wp chunk-major: i = tr*16 + q (coalesced LDG.128, conflict-free STS)
    {
        const float4* wsrc = (const float4*)Wp;
#pragma unroll
        for (int j = 0; j < 16; j++) {
            int i = t + j * 256;
            int tr = i >> 4, q = i & 15;
            sw4[q * 257 + tr] = wsrc[i];
        }
    }

#pragma unroll
    for (int j = 0; j < 4; j++) {
        int i = t + j * 256;
        int r = i >> 6, cc = i & 63;
        size_t rb = (size_t)(row0 + r) * NTC;
        float deg = 0.f, v = 0.f;
#pragma unroll
        for (int q = 0; q < KSPLIT; q++) {
            const float* Cq = g_Cp + (size_t)q * NN * NTC;
            deg += Cq[rb + HD];
            v += Cq[rb + cc];
        }
        nb[r][cc] = (deg > 0.5f) ? v / deg : 0.f;
    }
    __syncthreads();

    float tf[16];
    {
        float b = bp[t];
#pragma unroll
        for (int r = 0; r < 16; r++) tf[r] = b;
    }
#pragma unroll
    for (int q = 0; q < 16; q++) {
        float4 w = sw4[q * 257 + t];
#pragma unroll
        for (int r = 0; r < 16; r++) {
            float4 nv = *(const float4*)(&nb[r][q * 4]);
            tf[r] += nv.x * w.x + nv.y * w.y + nv.z * w.z + nv.w * w.w;
        }
    }

    float y[16];
#pragma unroll
    for (int r = 0; r < 16; r++) y[r] = x[(size_t)(row0 + r) * FD + t] + tf[r];

#pragma unroll
    for (int r = 0; r < 16; r++) {
        float s = y[r], q = y[r] * y[r];
#pragma unroll
        for (int o = 16; o > 0; o >>= 1) {
            s += __shfl_xor_sync(0xffffffffu, s, o);
            q += __shfl_xor_sync(0xffffffffu, q, o);
        }
        if (lane == 0) { pwS[warp][r] = s; pwQ[warp][r] = q; }
    }
    __syncthreads();
    if (t < 16) {
        float s = 0.f, q = 0.f;
#pragma unroll
        for (int w = 0; w < 8; w++) { s += pwS[w][t]; q += pwQ[w][t]; }
        float mu = s * (1.f / FD);
        float var = q * (1.f / FD) - mu * mu;
        muS[t] = mu;
        rsS[t] = rsqrtf(var + 1e-5f);
    }
    __syncthreads();

    const float g = gamma[t], b = beta[t];
#pragma unroll
    for (int r = 0; r < 16; r++)
        out[(size_t)(row0 + r) * FD + t] = g * (y[r] - muS[r]) * rsS[r] + b;
}

// ---------------------------------------------------------------------------
extern "C" void kernel_launch(void* const* d_in, const int* in_sizes, int n_in,
                              void* d_out, int out_size) {
    const float* x     = (const float*)d_in[0];
    const int*   adj   = (const int*)d_in[1];
    const float* Wt    = (const float*)d_in[2];
    const float* bt    = (const float*)d_in[3];
    // d_in[4] (Wa), d_in[5] (ba): mathematically irrelevant — softmax over
    // row-constant scores collapses to 1/deg regardless of s.
    const float* Wp    = (const float*)d_in[6];
    const float* bp    = (const float*)d_in[7];
    const float* gamma = (const float*)d_in[8];
    const float* beta  = (const float*)d_in[9];
    float* out = (float*)d_out;

    cudaFuncSetAttribute(k_adj_mm, cudaFuncAttributeMaxDynamicSharedMemorySize, SMEM_MM);
    cudaFuncSetAttribute(k_hmm, cudaFuncAttributeMaxDynamicSharedMemorySize, SMEM_HMM);
    cudaFuncSetAttribute(k_epi, cudaFuncAttributeMaxDynamicSharedMemorySize, SMEM_EPI);
    k_w<<<64, 256>>>(Wt);
    k_hmm<<<NN / BM, 256, SMEM_HMM>>>(x, bt);
    k_adj_mm<<<(NN / BM) * KSPLIT, 256, SMEM_MM>>>(adj);
    k_epi<<<NN / 16, 256, SMEM_EPI>>>(x, Wp, bp, gamma, beta, out);
}